// round 15
// baseline (speedup 1.0000x reference)
#include <cuda_runtime.h>
#include <cuda_bf16.h>
#include <cuda_fp16.h>
#include <cstdint>
#include <math.h>

#define Bq 128
#define Nq 196
#define Fq 512
#define Eq 512
#define Hq 512
#define Aq 512
#define Vq 30000
#define Tq 20
#define Lq 21

// ------------------------------------------------------------------
// Device scratch.  fp16 GEMM operands use p16: a field-swap involution
// within each 32-element K-group so fragment loads are LDS.128.
// ------------------------------------------------------------------
__device__ __half g_embh[Bq * Tq * Eq];        // [p16]
__device__ float  g_gfeat[Bq * Fq];
__device__ __half g_hh[Bq * Hq];               // [p16]
__device__ float  g_c[Bq * Hq];                // exact
__device__ __half g_fprojh[Bq * Nq * Aq];      // linear fp16
__device__ __half g_feath[Bq * Nq * Fq];       // [p16] - fproj A + ctx
__device__ __half g_xhh[Bq * 1536];            // [p16]
__device__ __half g_Wcath[2048 * 1536];        // [p16]
__device__ float  g_bcat[2048];
__device__ float  g_hpart[4 * Bq * 512];
__device__ float  g_gpart[8 * Bq * 2048];
__device__ float  g_skpart[16 * Bq * 512];
__device__ __half g_Whh[Aq * Hq];              // [p16]
__device__ __half g_Wfh[Aq * Fq];              // [p16]
__device__ __half g_outwh[Vq * Hq];            // [p16]
__device__ __half g_hallh[Tq * Bq * Hq];       // [p16]

// ------------------------------------------------------------------
// Helpers
// ------------------------------------------------------------------
__device__ __host__ __forceinline__ int p16q(int c) {
    return (((c >> 1) & 3) << 3) | (((c >> 3) & 3) << 1) | (c & 1);
}
__device__ __host__ __forceinline__ int p16(int i) {
    return (i & ~31) | p16q(i & 31);
}
__device__ __forceinline__ unsigned su32(const void* p) {
    unsigned a;
    asm("{ .reg .u64 t; cvta.to.shared.u64 t, %1; cvt.u32.u64 %0, t; }"
        : "=r"(a) : "l"(p));
    return a;
}
__device__ __forceinline__ void cpa16(unsigned d, const void* s) {
    asm volatile("cp.async.cg.shared.global [%0], [%1], 16;" :: "r"(d), "l"(s));
}
__device__ __forceinline__ float tanh_apx(float x) {
    float y;
    asm("tanh.approx.f32 %0, %1;" : "=f"(y) : "f"(x));
    return y;
}
__device__ __forceinline__ void mma_h(float* c, const unsigned* a, const unsigned* b) {
    asm volatile(
        "mma.sync.aligned.m16n8k16.row.col.f32.f16.f16.f32 "
        "{%0,%1,%2,%3},{%4,%5,%6,%7},{%8,%9},{%0,%1,%2,%3};"
        : "+f"(c[0]), "+f"(c[1]), "+f"(c[2]), "+f"(c[3])
        : "r"(a[0]), "r"(a[1]), "r"(a[2]), "r"(a[3]), "r"(b[0]), "r"(b[1]));
}

// ------------------------------------------------------------------
// fp16 tensor GEMM: BK=32, 3-stage cp.async, operands p16-permuted.
// C[M,N] = A[M,K] @ B[N,K]^T (+bias if SPLIT==1), fp32 accum.
// LOGIT: M-tile index = blockIdx.x + mofs (also the t for out scatter).
// ------------------------------------------------------------------
#define RS16 40

template<int BN, int SPLIT, bool NG, bool LOGIT, bool OHF>
__global__ __launch_bounds__(256, 1) void gemm_h(
    const __half* __restrict__ A, const __half* __restrict__ B,
    const float* __restrict__ bias, void* __restrict__ Cv,
    int N, int K, int ldc, int mofs)
{
    constexpr int JF = BN / 32;
    constexpr int STG = (128 + BN) * RS16;
    constexpr int BOFF = 128 * RS16;
    extern __shared__ __align__(16) __half smh[];

    const int tid = threadIdx.x;
    const int mtile = LOGIT ? (blockIdx.x + mofs) : blockIdx.y;
    const int bm = mtile * 128;
    const int bn = (LOGIT ? blockIdx.y : blockIdx.x) * BN;
    const int warp = tid >> 5, lane = tid & 31;
    const int wm = (warp & 1) * 64, wn = (warp >> 1) * (BN / 4);
    const int g = lane >> 2, t4 = lane & 3;
    const int kc = K / SPLIT;
    const int kbeg = blockIdx.z * kc;

    float acc[4][JF][4];
#pragma unroll
    for (int i = 0; i < 4; i++)
#pragma unroll
        for (int j = 0; j < JF; j++)
#pragma unroll
            for (int q = 0; q < 4; q++) acc[i][j][q] = 0.f;

    const unsigned sbase = su32(smh);
    auto issue = [&](int s, int k0) {
#pragma unroll
        for (int l = 0; l < 2; l++) {
            int i2 = tid + l * 256;
            int row = i2 >> 2, c8 = i2 & 3;
            cpa16(sbase + ((unsigned)s * STG + row * RS16 + c8 * 8) * 2,
                  A + (size_t)(bm + row) * K + k0 + c8 * 8);
        }
#pragma unroll
        for (int l = 0; l < BN / 64; l++) {
            int i2 = tid + l * 256;
            int row = i2 >> 2, c8 = i2 & 3;
            int rb = bn + row;
            if (NG) rb = rb < N ? rb : (N - 1);
            cpa16(sbase + ((unsigned)s * STG + BOFF + row * RS16 + c8 * 8) * 2,
                  B + (size_t)rb * K + k0 + c8 * 8);
        }
        asm volatile("cp.async.commit_group;");
    };

    const int nk = kc / 32;
    issue(0, kbeg);
    issue(1, kbeg + 32);
    for (int it = 0; it < nk; it++) {
        if (it == nk - 1) asm volatile("cp.async.wait_group 0;" ::: "memory");
        else              asm volatile("cp.async.wait_group 1;" ::: "memory");
        __syncthreads();
        if (it + 2 < nk) issue((it + 2) % 3, kbeg + (it + 2) * 32);
        const int s = it % 3;
        const __half* As = smh + s * STG;
        const __half* Bs = smh + s * STG + BOFF;

        uint4 aA[4], aB[4], bq[JF];
#pragma unroll
        for (int i = 0; i < 4; i++) {
            aA[i] = *(const uint4*)(As + (wm + i * 16 + g) * RS16 + t4 * 8);
            aB[i] = *(const uint4*)(As + (wm + i * 16 + 8 + g) * RS16 + t4 * 8);
        }
#pragma unroll
        for (int j = 0; j < JF; j++)
            bq[j] = *(const uint4*)(Bs + (wn + j * 8 + g) * RS16 + t4 * 8);

#pragma unroll
        for (int i = 0; i < 4; i++) {
            unsigned ua[4] = {aA[i].x, aB[i].x, aA[i].y, aB[i].y};
#pragma unroll
            for (int j = 0; j < JF; j++) {
                unsigned ub[2] = {bq[j].x, bq[j].y};
                mma_h(acc[i][j], ua, ub);
            }
        }
#pragma unroll
        for (int i = 0; i < 4; i++) {
            unsigned ua[4] = {aA[i].z, aB[i].z, aA[i].w, aB[i].w};
#pragma unroll
            for (int j = 0; j < JF; j++) {
                unsigned ub[2] = {bq[j].z, bq[j].w};
                mma_h(acc[i][j], ua, ub);
            }
        }
    }

    float* Cz = (SPLIT > 1) ? ((float*)Cv + (size_t)blockIdx.z * 128 * N) : (float*)Cv;
#pragma unroll
    for (int i = 0; i < 4; i++) {
        int r = wm + i * 16 + g;
#pragma unroll
        for (int j = 0; j < JF; j++) {
            int n = bn + wn + j * 8 + 2 * t4;
            if (NG && n >= N) continue;
            float bz0 = 0.f, bz1 = 0.f;
            if (SPLIT == 1) { bz0 = bias[n]; bz1 = bias[n + 1]; }
            float2 v0 = make_float2(acc[i][j][0] + bz0, acc[i][j][1] + bz1);
            float2 v1 = make_float2(acc[i][j][2] + bz0, acc[i][j][3] + bz1);
            if (OHF) {
                __half* Ch = (__half*)Cv;
                *(__half2*)(Ch + (size_t)(bm + r) * ldc + n) = __floats2half2_rn(v0.x, v0.y);
                *(__half2*)(Ch + (size_t)(bm + r + 8) * ldc + n) = __floats2half2_rn(v1.x, v1.y);
            } else if (LOGIT) {
                int tt = mtile;
                *(float2*)(Cz + (size_t)r * (Tq * (size_t)Vq) + (size_t)tt * Vq + n) = v0;
                *(float2*)(Cz + (size_t)(r + 8) * (Tq * (size_t)Vq) + (size_t)tt * Vq + n) = v1;
            } else if (SPLIT > 1) {
                *(float2*)(Cz + (size_t)r * N + n) = v0;
                *(float2*)(Cz + (size_t)(r + 8) * N + n) = v1;
            } else {
                *(float2*)(Cz + (size_t)(bm + r) * ldc + n) = v0;
                *(float2*)(Cz + (size_t)(bm + r + 8) * ldc + n) = v1;
            }
        }
    }
}

// ------------------------------------------------------------------
// fp32 split-K GEMM (prologue h0/c0)
// ------------------------------------------------------------------
template<int SPLIT>
__global__ __launch_bounds__(256) void gemm_sk(
    const float* __restrict__ A, const float* __restrict__ B,
    float* __restrict__ Cpart, int N, int K)
{
    __shared__ float As[16][132];
    __shared__ float Bs[16][132];
    const int tid = threadIdx.x;
    const int tx = tid & 15, ty = tid >> 4;
    const int n0 = blockIdx.x * 128;
    const int s = blockIdx.y;
    const int kc = K / SPLIT;
    const int kbeg = s * kc;

    float acc[8][8];
#pragma unroll
    for (int i = 0; i < 8; i++)
#pragma unroll
        for (int j = 0; j < 8; j++) acc[i][j] = 0.f;

    for (int k0 = kbeg; k0 < kbeg + kc; k0 += 16) {
#pragma unroll
        for (int l = 0; l < 2; l++) {
            int i2 = tid + l * 256;
            int m = i2 >> 2, c4 = i2 & 3;
            float4 v = *(const float4*)(A + (size_t)m * K + k0 + c4 * 4);
            As[c4 * 4 + 0][m] = v.x; As[c4 * 4 + 1][m] = v.y;
            As[c4 * 4 + 2][m] = v.z; As[c4 * 4 + 3][m] = v.w;
            float4 w = *(const float4*)(B + (size_t)(n0 + m) * K + k0 + c4 * 4);
            Bs[c4 * 4 + 0][m] = w.x; Bs[c4 * 4 + 1][m] = w.y;
            Bs[c4 * 4 + 2][m] = w.z; Bs[c4 * 4 + 3][m] = w.w;
        }
        __syncthreads();
#pragma unroll
        for (int kk = 0; kk < 16; kk++) {
            float4 a0 = *(const float4*)&As[kk][ty * 8];
            float4 a1 = *(const float4*)&As[kk][ty * 8 + 4];
            float4 b0 = *(const float4*)&Bs[kk][tx * 8];
            float4 b1 = *(const float4*)&Bs[kk][tx * 8 + 4];
            const float av[8] = {a0.x, a0.y, a0.z, a0.w, a1.x, a1.y, a1.z, a1.w};
            const float bv[8] = {b0.x, b0.y, b0.z, b0.w, b1.x, b1.y, b1.z, b1.w};
#pragma unroll
            for (int i = 0; i < 8; i++)
#pragma unroll
                for (int j = 0; j < 8; j++)
                    acc[i][j] = fmaf(av[i], bv[j], acc[i][j]);
        }
        __syncthreads();
    }

    float* Cp = Cpart + (size_t)s * 128 * N;
#pragma unroll
    for (int i = 0; i < 8; i++) {
        float* row = Cp + (size_t)(ty * 8 + i) * N + n0 + tx * 8;
        *(float4*)row = make_float4(acc[i][0], acc[i][1], acc[i][2], acc[i][3]);
        *(float4*)(row + 4) = make_float4(acc[i][4], acc[i][5], acc[i][6], acc[i][7]);
    }
}

__global__ void k_redh(__half* __restrict__ dst, const float* __restrict__ part,
                       const float* __restrict__ bias)
{
    int i = blockIdx.x * 256 + threadIdx.x;
    float acc = bias[i & 511];
#pragma unroll
    for (int s = 0; s < 16; s++) acc += part[s * 65536 + i];
    dst[p16(i)] = __float2half(acc);
}
__global__ void k_redf(float* __restrict__ dst, const float* __restrict__ part,
                       const float* __restrict__ bias)
{
    int i = blockIdx.x * 256 + threadIdx.x;
    float acc = bias[i & 511];
#pragma unroll
    for (int s = 0; s < 16; s++) acc += part[s * 65536 + i];
    dst[i] = acc;
}

// ------------------------------------------------------------------
// prep kernels
// ------------------------------------------------------------------
__global__ void k_cvtp16(__half* __restrict__ dst, const float* __restrict__ src, int n4)
{
    int i = blockIdx.x * 256 + threadIdx.x;
    if (i >= n4) return;
    float4 v = ((const float4*)src)[i];
    int base = i * 4;
    int grp = base & ~31, rem = base & 31;
    *(__half2*)(dst + grp + p16q(rem))     = __floats2half2_rn(v.x, v.y);
    *(__half2*)(dst + grp + p16q(rem + 2)) = __floats2half2_rn(v.z, v.w);
}

__global__ void k_prepw(const float* __restrict__ Wih, const float* __restrict__ Whh,
                        const float* __restrict__ bih, const float* __restrict__ bhh)
{
    int idx = blockIdx.x * blockDim.x + threadIdx.x;
    if (idx < 2048 * 1536) {
        int j = idx / 1536, col = idx % 1536;
        int cp = p16(col);
        float w = (cp < 1024) ? Wih[j * 1024 + cp] : Whh[j * 512 + (cp - 1024)];
        g_Wcath[idx] = __float2half(w);
    }
    if (idx < 2048) g_bcat[idx] = bih[idx] + bhh[idx];
}

__global__ void k_embed(const float* __restrict__ eW, const int* __restrict__ cap)
{
    int idx = blockIdx.x * blockDim.x + threadIdx.x;
    if (idx >= Bq * Tq * Eq) return;
    int e = idx & 511;
    int bt = idx >> 9;
    int b = bt / Tq, t = bt % Tq;
    int w = cap[b * Lq + t];
    g_embh[(bt << 9) + p16(e)] = (w == 0) ? __float2half(0.f)
                                          : __float2half(eW[(size_t)w * Eq + e]);
}

__global__ void k_gfeat(const float* __restrict__ feats)
{
    int b = blockIdx.x;
    const float* fe = feats + (size_t)b * Nq * Fq;
    for (int f = threadIdx.x; f < Fq; f += blockDim.x) {
        float acc = 0.f;
        for (int n = 0; n < Nq; n++) acc += fe[n * Fq + f];
        g_gfeat[b * Fq + f] = acc * (1.f / (float)Nq);
    }
}

// ------------------------------------------------------------------
// Fused attention (R13)
// ------------------------------------------------------------------
__global__ __launch_bounds__(256) void k_attn(
    const float* __restrict__ vw, const float* __restrict__ vb,
    const float* __restrict__ whb, int t)
{
    const int b = blockIdx.x;
    const int tid = threadIdx.x;
    const int lane = tid & 31;
    const int wrp = tid >> 5;
    __shared__ float hp[Aq];
    __shared__ float vv[Aq];
    __shared__ float sc[256];
    __shared__ float red[256];

    for (int i = tid; i < Aq; i += 256) {
        float s = whb[i];
#pragma unroll
        for (int s2 = 0; s2 < 4; s2++) s += g_hpart[s2 * 65536 + b * 512 + i];
        hp[i] = s;
        vv[i] = vw[i];
    }
    __syncthreads();

    const __half* fpb = g_fprojh + (size_t)b * Nq * Aq;
    for (int n = wrp; n < Nq; n += 8) {
        float s = 0.f;
        const uint4* row = (const uint4*)(fpb + n * Aq);
#pragma unroll
        for (int u = 0; u < 2; u++) {
            int a8 = lane + u * 32;
            uint4 pk = row[a8];
            const __half2* p2 = (const __half2*)&pk;
            const float* hv = &hp[a8 * 8];
            const float* vb2 = &vv[a8 * 8];
#pragma unroll
            for (int q = 0; q < 4; q++) {
                float2 f = __half22float2(p2[q]);
                s += vb2[q * 2]     * tanh_apx(f.x + hv[q * 2]);
                s += vb2[q * 2 + 1] * tanh_apx(f.y + hv[q * 2 + 1]);
            }
        }
#pragma unroll
        for (int o = 16; o; o >>= 1) s += __shfl_down_sync(0xffffffff, s, o);
        if (lane == 0) sc[n] = s + vb[0];
    }
    __syncthreads();

    float val = (tid < Nq) ? sc[tid] : -1e30f;
    red[tid] = val;
    __syncthreads();
    for (int o = 128; o; o >>= 1) {
        if (tid < o) red[tid] = fmaxf(red[tid], red[tid + o]);
        __syncthreads();
    }
    float mx = red[0];
    __syncthreads();
    float e = (tid < Nq) ? expf(val - mx) : 0.f;
    red[tid] = e;
    __syncthreads();
    for (int o = 128; o; o >>= 1) {
        if (tid < o) red[tid] += red[tid + o];
        __syncthreads();
    }
    float ssum = red[0];
    __syncthreads();
    if (tid < Nq) sc[tid] = e / ssum;
    __syncthreads();

    const __half2* fb = (const __half2*)(g_feath + (size_t)b * Nq * Fq);
    {
        int f2 = tid;
        float ax = 0.f, ay = 0.f;
#pragma unroll 4
        for (int n = 0; n < Nq; n++) {
            float2 v = __half22float2(fb[n * 256 + f2]);
            float w = sc[n];
            ax = fmaf(w, v.x, ax);
            ay = fmaf(w, v.y, ay);
        }
        ((__half2*)&g_xhh[b * 1536 + 512])[f2] = __floats2half2_rn(ax, ay);
    }
    for (int i = tid; i < 512; i += 256) {
        g_xhh[b * 1536 + i] = g_embh[((size_t)b * Tq + t) * Eq + i];
        g_xhh[b * 1536 + 1024 + i] = g_hh[b * Hq + i];
    }
}

// ------------------------------------------------------------------
// LSTM update
// ------------------------------------------------------------------
__global__ void k_lstm(int t)
{
    int idx = blockIdx.x * 256 + threadIdx.x;
    int b = idx >> 9, j = idx & 511;
    float v[4];
#pragma unroll
    for (int q = 0; q < 4; q++) {
        float s = g_bcat[q * 512 + j];
#pragma unroll
        for (int s2 = 0; s2 < 8; s2++)
            s += g_gpart[s2 * 262144 + b * 2048 + q * 512 + j];
        v[q] = s;
    }
    float i_ = 1.f / (1.f + expf(-v[0]));
    float f_ = 1.f / (1.f + expf(-v[1]));
    float gg = tanhf(v[2]);
    float o_ = 1.f / (1.f + expf(-v[3]));
    float cn = f_ * g_c[idx] + i_ * gg;
    g_c[idx] = cn;
    __half hn = __float2half(o_ * tanhf(cn));
    int jp = p16(j);
    g_hh[(b << 9) + jp] = hn;
    g_hallh[((size_t)t * 128 + b) * 512 + jp] = hn;
}

// ------------------------------------------------------------------
static float* sym(const void* s)
{
    void* p = nullptr;
    cudaGetSymbolAddress(&p, s);
    return (float*)p;
}
static __half* symh(const void* s)
{
    void* p = nullptr;
    cudaGetSymbolAddress(&p, s);
    return (__half*)p;
}

extern "C" void kernel_launch(void* const* d_in, const int* in_sizes, int n_in,
                              void* d_out, int out_size)
{
    const float* feats   = (const float*)d_in[0];
    const int*   caps    = (const int*)  d_in[1];
    const float* embW    = (const float*)d_in[2];
    const float* Wf_w    = (const float*)d_in[3];
    const float* Wf_b    = (const float*)d_in[4];
    const float* Wh_w    = (const float*)d_in[5];
    const float* Wh_b    = (const float*)d_in[6];
    const float* v_w     = (const float*)d_in[7];
    const float* v_b     = (const float*)d_in[8];
    const float* W_ih    = (const float*)d_in[9];
    const float* W_hh    = (const float*)d_in[10];
    const float* b_ih    = (const float*)d_in[11];
    const float* b_hh    = (const float*)d_in[12];
    const float* init_w  = (const float*)d_in[13];
    const float* init_b  = (const float*)d_in[14];
    const float* initc_w = (const float*)d_in[15];
    const float* initc_b = (const float*)d_in[16];
    const float* out_w   = (const float*)d_in[17];
    const float* out_b   = (const float*)d_in[18];
    float* out = (float*)d_out;

    float*  p_gf    = sym(g_gfeat);
    float*  p_c     = sym(g_c);
    float*  p_hpart = sym(g_hpart);
    float*  p_gpart = sym(g_gpart);
    float*  p_skp   = sym(g_skpart);
    __half* p_hh    = symh(g_hh);
    __half* p_feath = symh(g_feath);
    __half* p_Wfh   = symh(g_Wfh);
    __half* p_Whh   = symh(g_Whh);
    __half* p_outwh = symh(g_outwh);
    __half* p_hallh = symh(g_hallh);
    __half* p_xhh   = symh(g_xhh);
    __half* p_Wcath = symh(g_Wcath);
    void*   p_fprojh = nullptr; cudaGetSymbolAddress(&p_fprojh, g_fprojh);

    constexpr int SMH256 = 3 * (128 + 256) * RS16 * 2;  // 92,160 B
    constexpr int SMH128 = 3 * (128 + 128) * RS16 * 2;  // 61,440 B

    static cudaStream_t s2;
    static cudaEvent_t evP, evQ, evZ, evA[Tq];
    static bool init_done = false;
    if (!init_done) {
        cudaFuncSetAttribute((const void*)gemm_h<256, 1, false, false, true>,
                             cudaFuncAttributeMaxDynamicSharedMemorySize, SMH256);
        cudaFuncSetAttribute((const void*)gemm_h<256, 8, false, false, false>,
                             cudaFuncAttributeMaxDynamicSharedMemorySize, SMH256);
        cudaFuncSetAttribute((const void*)gemm_h<256, 1, true, true, false>,
                             cudaFuncAttributeMaxDynamicSharedMemorySize, SMH256);
        cudaFuncSetAttribute((const void*)gemm_h<128, 4, false, false, false>,
                             cudaFuncAttributeMaxDynamicSharedMemorySize, SMH128);
        cudaStreamCreateWithFlags(&s2, cudaStreamNonBlocking);
        cudaEventCreateWithFlags(&evP, cudaEventDisableTiming);
        cudaEventCreateWithFlags(&evQ, cudaEventDisableTiming);
        cudaEventCreateWithFlags(&evZ, cudaEventDisableTiming);
        for (int t = 0; t < Tq; t++)
            cudaEventCreateWithFlags(&evA[t], cudaEventDisableTiming);
        init_done = true;
    }

    // --- fork: loop/logits weight prep on s2, overlapped with fproj path ---
    cudaEventRecord(evP, 0);
    cudaStreamWaitEvent(s2, evP, 0);
    k_cvtp16<<<(Vq * Hq / 4 + 255) / 256, 256, 0, s2>>>(p_outwh, out_w, Vq * Hq / 4);
    k_cvtp16<<<(Aq * Hq / 4 + 255) / 256, 256, 0, s2>>>(p_Whh, Wh_w, Aq * Hq / 4);
    k_prepw<<<(2048 * 1536 + 255) / 256, 256, 0, s2>>>(W_ih, W_hh, b_ih, b_hh);
    cudaEventRecord(evQ, s2);

    // --- main prologue on stream 0 ---
    k_cvtp16<<<(Bq * Nq * Fq / 4 + 255) / 256, 256>>>(p_feath, feats, Bq * Nq * Fq / 4);
    k_cvtp16<<<(Aq * Fq / 4 + 255) / 256, 256>>>(p_Wfh, Wf_w, Aq * Fq / 4);
    k_embed<<<(Bq * Tq * Eq + 255) / 256, 256>>>(embW, caps);
    gemm_h<256, 1, false, false, true><<<dim3(2, 196, 1), 256, SMH256>>>(
        p_feath, p_Wfh, Wf_b, p_fprojh, 512, 512, 512, 0);
    k_gfeat<<<Bq, 256>>>(feats);

    gemm_sk<16><<<dim3(4, 16), 256>>>(p_gf, init_w, p_skp, 512, 512);
    k_redh<<<256, 256>>>(p_hh, p_skp, init_b);
    gemm_sk<16><<<dim3(4, 16), 256>>>(p_gf, initc_w, p_skp, 512, 512);
    k_redf<<<256, 256>>>(p_c, p_skp, initc_b);

    cudaStreamWaitEvent(0, evQ, 0);

    // --- recurrence, with per-step logits slice overlapped on s2 ---
    for (int t = 0; t < Tq; t++) {
        gemm_h<128, 4, false, false, false><<<dim3(4, 1, 4), 256, SMH128>>>(
            p_hh, p_Whh, nullptr, p_hpart, 512, 512, 0, 0);
        k_attn<<<Bq, 256>>>(v_w, v_b, Wh_b, t);
        gemm_h<256, 8, false, false, false><<<dim3(8, 1, 8), 256, SMH256>>>(
            p_xhh, p_Wcath, nullptr, p_gpart, 2048, 1536, 0, 0);
        k_lstm<<<256, 256>>>(t);
        cudaEventRecord(evA[t], 0);
        cudaStreamWaitEvent(s2, evA[t], 0);
        gemm_h<256, 1, true, true, false><<<dim3(1, (Vq + 255) / 256, 1), 256, SMH256, s2>>>(
            p_hallh, p_outwh, out_b, out, Vq, 512, 0, t);
    }

    // --- join: single event after last logits slice (s2 is in-order) ---
    cudaEventRecord(evZ, s2);
    cudaStreamWaitEvent(0, evZ, 0);
}

// round 16
// speedup vs baseline: 1.5871x; 1.5871x over previous
#include <cuda_runtime.h>
#include <cuda_bf16.h>
#include <cuda_fp16.h>
#include <cstdint>
#include <math.h>

#define Bq 128
#define Nq 196
#define Fq 512
#define Eq 512
#define Hq 512
#define Aq 512
#define Vq 30000
#define Tq 20
#define Lq 21

// ------------------------------------------------------------------
// Device scratch.  fp16 GEMM operands use p16: a field-swap involution
// within each 32-element K-group so fragment loads are LDS.128.
// ------------------------------------------------------------------
__device__ __half g_embh[Bq * Tq * Eq];        // [p16]
__device__ float  g_gfeat[Bq * Fq];
__device__ __half g_hh[Bq * Hq];               // [p16]
__device__ float  g_c[Bq * Hq];                // exact
__device__ __half g_fprojh[Bq * Nq * Aq];      // linear fp16
__device__ __half g_feath[Bq * Nq * Fq];       // [p16] - fproj A + ctx
__device__ __half g_xhh[Bq * 1536];            // [p16]
__device__ __half g_Wcath[2048 * 1536];        // [p16]
__device__ float  g_bcat[2048];
__device__ float  g_hpart[4 * Bq * 512];
__device__ float  g_gpart[8 * Bq * 2048];
__device__ float  g_skpart[16 * Bq * 512];
__device__ __half g_Whh[Aq * Hq];              // [p16]
__device__ __half g_Wfh[Aq * Fq];              // [p16]
__device__ __half g_outwh[Vq * Hq];            // [p16]
__device__ __half g_hallh[Tq * Bq * Hq];       // [p16]

// ------------------------------------------------------------------
// Helpers
// ------------------------------------------------------------------
__device__ __host__ __forceinline__ int p16q(int c) {
    return (((c >> 1) & 3) << 3) | (((c >> 3) & 3) << 1) | (c & 1);
}
__device__ __host__ __forceinline__ int p16(int i) {
    return (i & ~31) | p16q(i & 31);
}
__device__ __forceinline__ unsigned su32(const void* p) {
    unsigned a;
    asm("{ .reg .u64 t; cvta.to.shared.u64 t, %1; cvt.u32.u64 %0, t; }"
        : "=r"(a) : "l"(p));
    return a;
}
__device__ __forceinline__ void cpa16(unsigned d, const void* s) {
    asm volatile("cp.async.cg.shared.global [%0], [%1], 16;" :: "r"(d), "l"(s));
}
__device__ __forceinline__ float tanh_apx(float x) {
    float y;
    asm("tanh.approx.f32 %0, %1;" : "=f"(y) : "f"(x));
    return y;
}
__device__ __forceinline__ void mma_h(float* c, const unsigned* a, const unsigned* b) {
    asm volatile(
        "mma.sync.aligned.m16n8k16.row.col.f32.f16.f16.f32 "
        "{%0,%1,%2,%3},{%4,%5,%6,%7},{%8,%9},{%0,%1,%2,%3};"
        : "+f"(c[0]), "+f"(c[1]), "+f"(c[2]), "+f"(c[3])
        : "r"(a[0]), "r"(a[1]), "r"(a[2]), "r"(a[3]), "r"(b[0]), "r"(b[1]));
}

// ------------------------------------------------------------------
// fp16 tensor GEMM: BK=32, 3-stage cp.async, operands p16-permuted.
// RS16=32 halves (64 B row stride): conflict-free LDS.128 / STS.128.
// C[M,N] = A[M,K] @ B[N,K]^T (+bias if SPLIT==1), fp32 accum.
// LOGIT: blockIdx.x = t; scatter out[b][t][:].
// ------------------------------------------------------------------
#define RS16 32

template<int BN, int SPLIT, bool NG, bool LOGIT, bool OHF>
__global__ __launch_bounds__(256, 1) void gemm_h(
    const __half* __restrict__ A, const __half* __restrict__ B,
    const float* __restrict__ bias, void* __restrict__ Cv,
    int N, int K, int ldc)
{
    constexpr int JF = BN / 32;
    constexpr int STG = (128 + BN) * RS16;
    constexpr int BOFF = 128 * RS16;
    extern __shared__ __align__(16) __half smh[];

    const int tid = threadIdx.x;
    const int bm = (LOGIT ? blockIdx.x : blockIdx.y) * 128;
    const int bn = (LOGIT ? blockIdx.y : blockIdx.x) * BN;
    const int warp = tid >> 5, lane = tid & 31;
    const int wm = (warp & 1) * 64, wn = (warp >> 1) * (BN / 4);
    const int g = lane >> 2, t4 = lane & 3;
    const int kc = K / SPLIT;
    const int kbeg = blockIdx.z * kc;

    float acc[4][JF][4];
#pragma unroll
    for (int i = 0; i < 4; i++)
#pragma unroll
        for (int j = 0; j < JF; j++)
#pragma unroll
            for (int q = 0; q < 4; q++) acc[i][j][q] = 0.f;

    const unsigned sbase = su32(smh);
    auto issue = [&](int s, int k0) {
#pragma unroll
        for (int l = 0; l < 2; l++) {
            int i2 = tid + l * 256;
            int row = i2 >> 2, c8 = i2 & 3;
            cpa16(sbase + ((unsigned)s * STG + row * RS16 + c8 * 8) * 2,
                  A + (size_t)(bm + row) * K + k0 + c8 * 8);
        }
#pragma unroll
        for (int l = 0; l < BN / 64; l++) {
            int i2 = tid + l * 256;
            int row = i2 >> 2, c8 = i2 & 3;
            int rb = bn + row;
            if (NG) rb = rb < N ? rb : (N - 1);
            cpa16(sbase + ((unsigned)s * STG + BOFF + row * RS16 + c8 * 8) * 2,
                  B + (size_t)rb * K + k0 + c8 * 8);
        }
        asm volatile("cp.async.commit_group;");
    };

    const int nk = kc / 32;
    issue(0, kbeg);
    issue(1, kbeg + 32);
    for (int it = 0; it < nk; it++) {
        if (it == nk - 1) asm volatile("cp.async.wait_group 0;" ::: "memory");
        else              asm volatile("cp.async.wait_group 1;" ::: "memory");
        __syncthreads();
        if (it + 2 < nk) issue((it + 2) % 3, kbeg + (it + 2) * 32);
        const int s = it % 3;
        const __half* As = smh + s * STG;
        const __half* Bs = smh + s * STG + BOFF;

        uint4 aA[4], aB[4], bq[JF];
#pragma unroll
        for (int i = 0; i < 4; i++) {
            aA[i] = *(const uint4*)(As + (wm + i * 16 + g) * RS16 + t4 * 8);
            aB[i] = *(const uint4*)(As + (wm + i * 16 + 8 + g) * RS16 + t4 * 8);
        }
#pragma unroll
        for (int j = 0; j < JF; j++)
            bq[j] = *(const uint4*)(Bs + (wn + j * 8 + g) * RS16 + t4 * 8);

#pragma unroll
        for (int i = 0; i < 4; i++) {
            unsigned ua[4] = {aA[i].x, aB[i].x, aA[i].y, aB[i].y};
#pragma unroll
            for (int j = 0; j < JF; j++) {
                unsigned ub[2] = {bq[j].x, bq[j].y};
                mma_h(acc[i][j], ua, ub);
            }
        }
#pragma unroll
        for (int i = 0; i < 4; i++) {
            unsigned ua[4] = {aA[i].z, aB[i].z, aA[i].w, aB[i].w};
#pragma unroll
            for (int j = 0; j < JF; j++) {
                unsigned ub[2] = {bq[j].z, bq[j].w};
                mma_h(acc[i][j], ua, ub);
            }
        }
    }

    float* Cz = (SPLIT > 1) ? ((float*)Cv + (size_t)blockIdx.z * 128 * N) : (float*)Cv;
#pragma unroll
    for (int i = 0; i < 4; i++) {
        int r = wm + i * 16 + g;
#pragma unroll
        for (int j = 0; j < JF; j++) {
            int n = bn + wn + j * 8 + 2 * t4;
            if (NG && n >= N) continue;
            float bz0 = 0.f, bz1 = 0.f;
            if (SPLIT == 1) { bz0 = bias[n]; bz1 = bias[n + 1]; }
            float2 v0 = make_float2(acc[i][j][0] + bz0, acc[i][j][1] + bz1);
            float2 v1 = make_float2(acc[i][j][2] + bz0, acc[i][j][3] + bz1);
            if (OHF) {
                __half* Ch = (__half*)Cv;
                *(__half2*)(Ch + (size_t)(bm + r) * ldc + n) = __floats2half2_rn(v0.x, v0.y);
                *(__half2*)(Ch + (size_t)(bm + r + 8) * ldc + n) = __floats2half2_rn(v1.x, v1.y);
            } else if (LOGIT) {
                int tt = blockIdx.x;
                *(float2*)(Cz + (size_t)r * (Tq * (size_t)Vq) + (size_t)tt * Vq + n) = v0;
                *(float2*)(Cz + (size_t)(r + 8) * (Tq * (size_t)Vq) + (size_t)tt * Vq + n) = v1;
            } else if (SPLIT > 1) {
                *(float2*)(Cz + (size_t)r * N + n) = v0;
                *(float2*)(Cz + (size_t)(r + 8) * N + n) = v1;
            } else {
                *(float2*)(Cz + (size_t)(bm + r) * ldc + n) = v0;
                *(float2*)(Cz + (size_t)(bm + r + 8) * ldc + n) = v1;
            }
        }
    }
}

// ------------------------------------------------------------------
// fp32 split-K GEMM (prologue h0/c0)
// ------------------------------------------------------------------
template<int SPLIT>
__global__ __launch_bounds__(256) void gemm_sk(
    const float* __restrict__ A, const float* __restrict__ B,
    float* __restrict__ Cpart, int N, int K)
{
    __shared__ float As[16][132];
    __shared__ float Bs[16][132];
    const int tid = threadIdx.x;
    const int tx = tid & 15, ty = tid >> 4;
    const int n0 = blockIdx.x * 128;
    const int s = blockIdx.y;
    const int kc = K / SPLIT;
    const int kbeg = s * kc;

    float acc[8][8];
#pragma unroll
    for (int i = 0; i < 8; i++)
#pragma unroll
        for (int j = 0; j < 8; j++) acc[i][j] = 0.f;

    for (int k0 = kbeg; k0 < kbeg + kc; k0 += 16) {
#pragma unroll
        for (int l = 0; l < 2; l++) {
            int i2 = tid + l * 256;
            int m = i2 >> 2, c4 = i2 & 3;
            float4 v = *(const float4*)(A + (size_t)m * K + k0 + c4 * 4);
            As[c4 * 4 + 0][m] = v.x; As[c4 * 4 + 1][m] = v.y;
            As[c4 * 4 + 2][m] = v.z; As[c4 * 4 + 3][m] = v.w;
            float4 w = *(const float4*)(B + (size_t)(n0 + m) * K + k0 + c4 * 4);
            Bs[c4 * 4 + 0][m] = w.x; Bs[c4 * 4 + 1][m] = w.y;
            Bs[c4 * 4 + 2][m] = w.z; Bs[c4 * 4 + 3][m] = w.w;
        }
        __syncthreads();
#pragma unroll
        for (int kk = 0; kk < 16; kk++) {
            float4 a0 = *(const float4*)&As[kk][ty * 8];
            float4 a1 = *(const float4*)&As[kk][ty * 8 + 4];
            float4 b0 = *(const float4*)&Bs[kk][tx * 8];
            float4 b1 = *(const float4*)&Bs[kk][tx * 8 + 4];
            const float av[8] = {a0.x, a0.y, a0.z, a0.w, a1.x, a1.y, a1.z, a1.w};
            const float bv[8] = {b0.x, b0.y, b0.z, b0.w, b1.x, b1.y, b1.z, b1.w};
#pragma unroll
            for (int i = 0; i < 8; i++)
#pragma unroll
                for (int j = 0; j < 8; j++)
                    acc[i][j] = fmaf(av[i], bv[j], acc[i][j]);
        }
        __syncthreads();
    }

    float* Cp = Cpart + (size_t)s * 128 * N;
#pragma unroll
    for (int i = 0; i < 8; i++) {
        float* row = Cp + (size_t)(ty * 8 + i) * N + n0 + tx * 8;
        *(float4*)row = make_float4(acc[i][0], acc[i][1], acc[i][2], acc[i][3]);
        *(float4*)(row + 4) = make_float4(acc[i][4], acc[i][5], acc[i][6], acc[i][7]);
    }
}

__global__ void k_redh(__half* __restrict__ dst, const float* __restrict__ part,
                       const float* __restrict__ bias)
{
    int i = blockIdx.x * 256 + threadIdx.x;
    float acc = bias[i & 511];
#pragma unroll
    for (int s = 0; s < 16; s++) acc += part[s * 65536 + i];
    dst[p16(i)] = __float2half(acc);
}
__global__ void k_redf(float* __restrict__ dst, const float* __restrict__ part,
                       const float* __restrict__ bias)
{
    int i = blockIdx.x * 256 + threadIdx.x;
    float acc = bias[i & 511];
#pragma unroll
    for (int s = 0; s < 16; s++) acc += part[s * 65536 + i];
    dst[i] = acc;
}

// ------------------------------------------------------------------
// prep kernels
// ------------------------------------------------------------------
__global__ void k_cvtp16(__half* __restrict__ dst, const float* __restrict__ src, int n4)
{
    int i = blockIdx.x * 256 + threadIdx.x;
    if (i >= n4) return;
    float4 v = ((const float4*)src)[i];
    int base = i * 4;
    int grp = base & ~31, rem = base & 31;
    *(__half2*)(dst + grp + p16q(rem))     = __floats2half2_rn(v.x, v.y);
    *(__half2*)(dst + grp + p16q(rem + 2)) = __floats2half2_rn(v.z, v.w);
}

__global__ void k_prepw(const float* __restrict__ Wih, const float* __restrict__ Whh,
                        const float* __restrict__ bih, const float* __restrict__ bhh)
{
    int idx = blockIdx.x * blockDim.x + threadIdx.x;
    if (idx < 2048 * 1536) {
        int j = idx / 1536, col = idx % 1536;
        int cp = p16(col);
        float w = (cp < 1024) ? Wih[j * 1024 + cp] : Whh[j * 512 + (cp - 1024)];
        g_Wcath[idx] = __float2half(w);
    }
    if (idx < 2048) g_bcat[idx] = bih[idx] + bhh[idx];
}

__global__ void k_embed(const float* __restrict__ eW, const int* __restrict__ cap)
{
    int idx = blockIdx.x * blockDim.x + threadIdx.x;
    if (idx >= Bq * Tq * Eq) return;
    int e = idx & 511;
    int bt = idx >> 9;
    int b = bt / Tq, t = bt % Tq;
    int w = cap[b * Lq + t];
    g_embh[(bt << 9) + p16(e)] = (w == 0) ? __float2half(0.f)
                                          : __float2half(eW[(size_t)w * Eq + e]);
}

__global__ void k_gfeat(const float* __restrict__ feats)
{
    int b = blockIdx.x;
    const float* fe = feats + (size_t)b * Nq * Fq;
    for (int f = threadIdx.x; f < Fq; f += blockDim.x) {
        float acc = 0.f;
        for (int n = 0; n < Nq; n++) acc += fe[n * Fq + f];
        g_gfeat[b * Fq + f] = acc * (1.f / (float)Nq);
    }
}

// ------------------------------------------------------------------
// Fused attention, 512 threads: scores over 16 warps, ctx split over
// two n-half-ranges (partials combined in smem).  One block per b.
// ------------------------------------------------------------------
__global__ __launch_bounds__(512) void k_attn(
    const float* __restrict__ vw, const float* __restrict__ vb,
    const float* __restrict__ whb, int t)
{
    const int b = blockIdx.x;
    const int tid = threadIdx.x;
    const int lane = tid & 31;
    const int wrp = tid >> 5;
    __shared__ float hp[Aq];
    __shared__ float vv[Aq];
    __shared__ float sc[256];
    __shared__ float red[512];
    __shared__ float2 ctxp[2][256];

    for (int i = tid; i < Aq; i += 512) {
        float s = whb[i];
#pragma unroll
        for (int s2 = 0; s2 < 4; s2++) s += g_hpart[s2 * 65536 + b * 512 + i];
        hp[i] = s;
        vv[i] = vw[i];
    }
    __syncthreads();

    const __half* fpb = g_fprojh + (size_t)b * Nq * Aq;
    for (int n = wrp; n < Nq; n += 16) {
        float s = 0.f;
        const uint4* row = (const uint4*)(fpb + n * Aq);
#pragma unroll
        for (int u = 0; u < 2; u++) {
            int a8 = lane + u * 32;
            uint4 pk = row[a8];
            const __half2* p2 = (const __half2*)&pk;
            const float* hv = &hp[a8 * 8];
            const float* vb2 = &vv[a8 * 8];
#pragma unroll
            for (int q = 0; q < 4; q++) {
                float2 f = __half22float2(p2[q]);
                s += vb2[q * 2]     * tanh_apx(f.x + hv[q * 2]);
                s += vb2[q * 2 + 1] * tanh_apx(f.y + hv[q * 2 + 1]);
            }
        }
#pragma unroll
        for (int o = 16; o; o >>= 1) s += __shfl_down_sync(0xffffffff, s, o);
        if (lane == 0) sc[n] = s + vb[0];
    }
    __syncthreads();

    float val = (tid < Nq) ? sc[tid] : -1e30f;
    red[tid] = val;
    __syncthreads();
    for (int o = 256; o; o >>= 1) {
        if (tid < o) red[tid] = fmaxf(red[tid], red[tid + o]);
        __syncthreads();
    }
    float mx = red[0];
    __syncthreads();
    float e = (tid < Nq) ? expf(val - mx) : 0.f;
    red[tid] = e;
    __syncthreads();
    for (int o = 256; o; o >>= 1) {
        if (tid < o) red[tid] += red[tid + o];
        __syncthreads();
    }
    float ssum = red[0];
    __syncthreads();
    if (tid < Nq) sc[tid] = e / ssum;
    __syncthreads();

    // ctx: thread (half, f2) accumulates n in [half*98, half*98+98)
    const __half2* fb = (const __half2*)(g_feath + (size_t)b * Nq * Fq);
    {
        int f2 = tid & 255;
        int hf = tid >> 8;
        int n0 = hf * 98;
        float ax = 0.f, ay = 0.f;
#pragma unroll 4
        for (int n = n0; n < n0 + 98; n++) {
            float2 v = __half22float2(fb[n * 256 + f2]);
            float w = sc[n];
            ax = fmaf(w, v.x, ax);
            ay = fmaf(w, v.y, ay);
        }
        ctxp[hf][f2] = make_float2(ax, ay);
    }
    __syncthreads();
    if (tid < 256) {
        float2 a = ctxp[0][tid], c2 = ctxp[1][tid];
        ((__half2*)&g_xhh[b * 1536 + 512])[tid] =
            __floats2half2_rn(a.x + c2.x, a.y + c2.y);
    }
    for (int i = tid; i < 512; i += 512) {
        g_xhh[b * 1536 + i] = g_embh[((size_t)b * Tq + t) * Eq + i];
        g_xhh[b * 1536 + 1024 + i] = g_hh[b * Hq + i];
    }
}

// ------------------------------------------------------------------
// LSTM update
// ------------------------------------------------------------------
__global__ void k_lstm(int t)
{
    int idx = blockIdx.x * 256 + threadIdx.x;
    int b = idx >> 9, j = idx & 511;
    float v[4];
#pragma unroll
    for (int q = 0; q < 4; q++) {
        float s = g_bcat[q * 512 + j];
#pragma unroll
        for (int s2 = 0; s2 < 8; s2++)
            s += g_gpart[s2 * 262144 + b * 2048 + q * 512 + j];
        v[q] = s;
    }
    float i_ = 1.f / (1.f + expf(-v[0]));
    float f_ = 1.f / (1.f + expf(-v[1]));
    float gg = tanhf(v[2]);
    float o_ = 1.f / (1.f + expf(-v[3]));
    float cn = f_ * g_c[idx] + i_ * gg;
    g_c[idx] = cn;
    __half hn = __float2half(o_ * tanhf(cn));
    int jp = p16(j);
    g_hh[(b << 9) + jp] = hn;
    g_hallh[((size_t)t * 128 + b) * 512 + jp] = hn;
}

// ------------------------------------------------------------------
static float* sym(const void* s)
{
    void* p = nullptr;
    cudaGetSymbolAddress(&p, s);
    return (float*)p;
}
static __half* symh(const void* s)
{
    void* p = nullptr;
    cudaGetSymbolAddress(&p, s);
    return (__half*)p;
}

extern "C" void kernel_launch(void* const* d_in, const int* in_sizes, int n_in,
                              void* d_out, int out_size)
{
    const float* feats   = (const float*)d_in[0];
    const int*   caps    = (const int*)  d_in[1];
    const float* embW    = (const float*)d_in[2];
    const float* Wf_w    = (const float*)d_in[3];
    const float* Wf_b    = (const float*)d_in[4];
    const float* Wh_w    = (const float*)d_in[5];
    const float* Wh_b    = (const float*)d_in[6];
    const float* v_w     = (const float*)d_in[7];
    const float* v_b     = (const float*)d_in[8];
    const float* W_ih    = (const float*)d_in[9];
    const float* W_hh    = (const float*)d_in[10];
    const float* b_ih    = (const float*)d_in[11];
    const float* b_hh    = (const float*)d_in[12];
    const float* init_w  = (const float*)d_in[13];
    const float* init_b  = (const float*)d_in[14];
    const float* initc_w = (const float*)d_in[15];
    const float* initc_b = (const float*)d_in[16];
    const float* out_w   = (const float*)d_in[17];
    const float* out_b   = (const float*)d_in[18];
    float* out = (float*)d_out;

    float*  p_gf    = sym(g_gfeat);
    float*  p_c     = sym(g_c);
    float*  p_hpart = sym(g_hpart);
    float*  p_gpart = sym(g_gpart);
    float*  p_skp   = sym(g_skpart);
    __half* p_hh    = symh(g_hh);
    __half* p_feath = symh(g_feath);
    __half* p_Wfh   = symh(g_Wfh);
    __half* p_Whh   = symh(g_Whh);
    __half* p_outwh = symh(g_outwh);
    __half* p_hallh = symh(g_hallh);
    __half* p_xhh   = symh(g_xhh);
    __half* p_Wcath = symh(g_Wcath);
    void*   p_fprojh = nullptr; cudaGetSymbolAddress(&p_fprojh, g_fprojh);

    constexpr int SMH256 = 3 * (128 + 256) * RS16 * 2;  // 73,728 B
    constexpr int SMH128 = 3 * (128 + 128) * RS16 * 2;  // 49,152 B
    static bool init_done = false;
    if (!init_done) {
        cudaFuncSetAttribute((const void*)gemm_h<256, 1, false, false, true>,
                             cudaFuncAttributeMaxDynamicSharedMemorySize, SMH256);
        cudaFuncSetAttribute((const void*)gemm_h<256, 8, false, false, false>,
                             cudaFuncAttributeMaxDynamicSharedMemorySize, SMH256);
        cudaFuncSetAttribute((const void*)gemm_h<256, 1, true, true, false>,
                             cudaFuncAttributeMaxDynamicSharedMemorySize, SMH256);
        cudaFuncSetAttribute((const void*)gemm_h<128, 4, false, false, false>,
                             cudaFuncAttributeMaxDynamicSharedMemorySize, SMH128);
        init_done = true;
    }

    // --- prologue (fproj GEMM is launch #4 for ncu capture) ---
    k_cvtp16<<<(Bq * Nq * Fq / 4 + 255) / 256, 256>>>(p_feath, feats, Bq * Nq * Fq / 4);
    k_cvtp16<<<(Aq * Fq / 4 + 255) / 256, 256>>>(p_Wfh, Wf_w, Aq * Fq / 4);
    k_embed<<<(Bq * Tq * Eq + 255) / 256, 256>>>(embW, caps);
    gemm_h<256, 1, false, false, true><<<dim3(2, 196, 1), 256, SMH256>>>(
        p_feath, p_Wfh, Wf_b, p_fprojh, 512, 512, 512);

    k_cvtp16<<<(Vq * Hq / 4 + 255) / 256, 256>>>(p_outwh, out_w, Vq * Hq / 4);
    k_cvtp16<<<(Aq * Hq / 4 + 255) / 256, 256>>>(p_Whh, Wh_w, Aq * Hq / 4);
    k_prepw<<<(2048 * 1536 + 255) / 256, 256>>>(W_ih, W_hh, b_ih, b_hh);
    k_gfeat<<<Bq, 256>>>(feats);

    gemm_sk<16><<<dim3(4, 16), 256>>>(p_gf, init_w, p_skp, 512, 512);
    k_redh<<<256, 256>>>(p_hh, p_skp, init_b);
    gemm_sk<16><<<dim3(4, 16), 256>>>(p_gf, initc_w, p_skp, 512, 512);
    k_redf<<<256, 256>>>(p_c, p_skp, initc_b);

    // --- recurrence ---
    for (int t = 0; t < Tq; t++) {
        gemm_h<128, 4, false, false, false><<<dim3(4, 1, 4), 256, SMH128>>>(
            p_hh, p_Whh, nullptr, p_hpart, 512, 512, 0);
        k_attn<<<Bq, 512>>>(v_w, v_b, Wh_b, t);
        gemm_h<256, 8, false, false, false><<<dim3(8, 1, 8), 256, SMH256>>>(
            p_xhh, p_Wcath, nullptr, p_gpart, 2048, 1536, 0);
        k_lstm<<<256, 256>>>(t);
    }

    // --- batched logits: grid (t fastest, n-tile) ---
    gemm_h<256, 1, true, true, false><<<dim3(Tq, (Vq + 255) / 256, 1), 256, SMH256>>>(
        p_hallh, p_outwh, out_b, out, Vq, 512, 0);
}